// round 15
// baseline (speedup 1.0000x reference)
#include <cuda_runtime.h>
#include <cuda_bf16.h>
#include <cstdint>

// MaxUnpooling2D: B=16, H=64, W=64, C=256, SIZE=(2,2) -> out Bx128x128x256.
// Expand/gather inversion: each output cell has exactly one candidate writer
// (its pooled parent), so each thread writes all 4 window cells of its input
// group, selecting update-or-zero per lane. No atomics, no zero-init.
//
// Measured history (all ~flat => DRAM mixed-stream ceiling ~75% of spec):
//   R6  V=2 __ldcs loads:        57.8us kern / 63.8us bench, DRAM 75.3%
//   R8  V=4 __ldcs loads:        57.3us kern / 64.2us bench, DRAM 75.6%
//   R11 V=2 evict-normal loads:  58.8us kern / 63.8us bench, DRAM 73.8%
// This round: reorganize each thread to own 8 CONSECUTIVE channels (same
// 64B/thread as R6) so every window-cell store is one 32B-aligned 32B write,
// letting nvcc emit STG.256/LDG.256 (Blackwell 256-bit global access).
// Worst case the compiler splits into 2x128-bit -> identical to R6.

static constexpr int H  = 64;
static constexpr int W  = 64;
static constexpr int C  = 256;
static constexpr int HO = 128;
static constexpr int WO = 128;
static constexpr int C8 = C / 8;                        // 32 groups per (b,h,w)
static constexpr unsigned OUT_PER_BATCH = HO * WO * C;  // floats per batch

static constexpr int THREADS = 256;

struct alignas(32) F8 { float4 a, b; };   // 8 floats, 32B aligned
struct alignas(32) I8 { int4   a, b; };   // 8 ints,   32B aligned

__global__ __launch_bounds__(THREADS)
void max_unpool_expand_kernel(const F8* __restrict__ updates8,
                              const I8* __restrict__ mask8,
                              float*    __restrict__ out,
                              unsigned n8)
{
    unsigned idx = blockIdx.x * THREADS + threadIdx.x;   // one 8-channel group
    if (idx >= n8) return;

    // Decode (b, h, w, c8): C8=32 -> 5 bits, W=64 -> 6, H=64 -> 6.
    unsigned c8 = idx & (C8 - 1);
    unsigned w  = (idx >> 5)  & (W - 1);
    unsigned h  = (idx >> 11) & (H - 1);
    unsigned b  =  idx >> 17;              // works for any batch count

    // Front-batch all 4 independent 16B loads (MLP=4), streaming policy
    // (best measured: __ldcs on loads, R6).
    int4   ma = __ldcs(&mask8[idx].a);
    int4   mb = __ldcs(&mask8[idx].b);
    float4 ua = __ldcs(&updates8[idx].a);
    float4 ub = __ldcs(&updates8[idx].b);

    int c  = (int)(c8 << 3);               // first channel of the group
    int y0 = (int)(h << 1);
    int x0 = (int)(w << 1);
    unsigned outBatch = b * OUT_PER_BATCH; // in floats

    #pragma unroll
    for (int dy = 0; dy < 2; ++dy) {
        // Row base for (y0+dy, x0), channel c: ((y*WO + x0)*C) + c
        int rowBase = ((((y0 + dy) << 7) + x0) << 8) + c;
        #pragma unroll
        for (int dx = 0; dx < 2; ++dx) {
            int base = rowBase + dx * C;   // dx=1 -> +C floats (next column)
            F8 r;
            r.a.x = (ma.x == base    ) ? ua.x : 0.0f;
            r.a.y = (ma.y == base + 1) ? ua.y : 0.0f;
            r.a.z = (ma.z == base + 2) ? ua.z : 0.0f;
            r.a.w = (ma.w == base + 3) ? ua.w : 0.0f;
            r.b.x = (mb.x == base + 4) ? ub.x : 0.0f;
            r.b.y = (mb.y == base + 5) ? ub.y : 0.0f;
            r.b.z = (mb.z == base + 6) ? ub.z : 0.0f;
            r.b.w = (mb.w == base + 7) ? ub.w : 0.0f;
            // One 32B-aligned 32B store per window cell (STG.256 candidate).
            // Output written exactly once, never re-read.
            *reinterpret_cast<F8*>(&out[outBatch + (unsigned)base]) = r;
        }
    }
}

extern "C" void kernel_launch(void* const* d_in, const int* in_sizes, int n_in,
                              void* d_out, int out_size)
{
    const F8* updates8 = (const F8*)d_in[0];  // float32 updates
    const I8* mask8    = (const I8*)d_in[1];  // int32 mask
    float*    out      = (float*)d_out;

    unsigned n8   = (unsigned)(in_sizes[0] / 8);       // 8-channel groups
    unsigned grid = (n8 + THREADS - 1) / THREADS;      // 8192 @ B=16

    max_unpool_expand_kernel<<<grid, THREADS>>>(updates8, mask8, out, n8);
}